// round 9
// baseline (speedup 1.0000x reference)
#include <cuda_runtime.h>
#include <cstdint>

// SpatialTransformer bilinear flow warp — R8 + flow pipelining + cache hints.
// src:  [B,H,W,1] f32,  flow: [B,H,W,2] f32,  out: [B,H,W,1] f32
// B=32, H=768, W=768.
//
// Operating point (proven): 32x16 tile / 128-thread block; lane -> 32
// consecutive x, warp -> 4-row strip; clamp-free fast path (R8).
// New in R9:
//   - flow loads software-pipelined one row ahead (breaks the per-row
//     serial chain: flow DRAM miss no longer precedes each row's gathers)
//   - __ldcs on flow / __stcs on out: streaming data evicts first, keeping
//     L1 capacity for src gather lines (raises gather hit rate)

#define BB 32
#define HH 768
#define WW 768
#define HW (HH * WW)

__global__ __launch_bounds__(128) void warp_kernel(
    const float* __restrict__ src,
    const float* __restrict__ flow,
    float* __restrict__ out)
{
    const int tx = threadIdx.x;
    const int xg = blockIdx.x * 32 + (tx & 31);       // global x
    const int yb = blockIdx.y * 16 + (tx >> 5) * 4;   // first of 4 rows
    const int b  = blockIdx.z;

    const float* img  = src + b * HW;
    const int    pix0 = (b * HH + yb) * WW + xg;
    const float  xgf  = (float)xg;

    // prefetch row 0 flow (streaming hint: no reuse, evict first)
    float2 f = __ldcs(reinterpret_cast<const float2*>(flow + (size_t)pix0 * 2));

    #pragma unroll
    for (int r = 0; r < 4; r++) {
        // prefetch next row's flow before consuming this row's
        float2 fnext;
        if (r < 3)
            fnext = __ldcs(reinterpret_cast<const float2*>(
                flow + (size_t)(pix0 + (r + 1) * WW) * 2));

        const int y   = yb + r;
        const int pix = pix0 + r * WW;

        const float gx = xgf + f.x;
        const float gy = (float)y + f.y;

        const float x0f = floorf(gx);
        const float y0f = floorf(gy);
        const float x1f = x0f + 1.0f;
        const float y1f = y0f + 1.0f;

        // weights from UNCLIPPED corners — exact reference formulation
        const float dx1 = x1f - gx;
        const float dx0 = gx - x0f;
        const float dy1 = y1f - gy;
        const float dy0 = gy - y0f;

        const float wa = dx1 * dy1;
        const float wb = dx0 * dy1;
        const float wc = dx1 * dy0;
        const float wd = dx0 * dy0;

        const int ix0 = (int)x0f;
        const int iy0 = (int)y0f;

        float va, vb, vc, vd;
        // fast iff ix0 in [0, W-2] and iy0 in [0, H-2]: clamps are identity
        if (((unsigned)ix0 < (WW - 1)) & ((unsigned)iy0 < (HH - 1))) {
            const float* p = img + iy0 * WW + ix0;
            va = __ldg(p);
            vb = __ldg(p + 1);
            vc = __ldg(p + WW);
            vd = __ldg(p + WW + 1);
        } else {
            // exact reference slow path (clamped indices)
            const int xi0 = (int)fminf(fmaxf(x0f, 0.0f), (float)(WW - 1));
            const int xi1 = (int)fminf(fmaxf(x1f, 0.0f), (float)(WW - 1));
            const int yi0 = (int)fminf(fmaxf(y0f, 0.0f), (float)(HH - 1));
            const int yi1 = (int)fminf(fmaxf(y1f, 0.0f), (float)(HH - 1));
            const int g0 = yi0 * WW;
            const int g1 = yi1 * WW;
            va = __ldg(img + g0 + xi0);
            vb = __ldg(img + g0 + xi1);
            vc = __ldg(img + g1 + xi0);
            vd = __ldg(img + g1 + xi1);
        }

        // streaming store (no L1 allocate pressure)
        __stcs(out + pix, wa * va + wb * vb + wc * vc + wd * vd);

        f = fnext;
    }
}

extern "C" void kernel_launch(void* const* d_in, const int* in_sizes, int n_in,
                              void* d_out, int out_size)
{
    const float* src  = (const float*)d_in[0];
    const float* flow = (const float*)d_in[1];
    float* out = (float*)d_out;

    dim3 grid(WW / 32, HH / 16, BB);   // (24, 48, 32)
    warp_kernel<<<grid, 128>>>(src, flow, out);
}